// round 1
// baseline (speedup 1.0000x reference)
#include <cuda_runtime.h>
#include <math.h>
#include <float.h>

#define BSZ   256
#define NCOLS 512
#define MROW  32768
#define DIM   512
#define KNEG  10
#define MARGIN_F 0.1f
#define EPS_F 1e-6f
#define TMARGIN_F 0.31622776601683794f

// ---------------- scratch (device globals; no allocation allowed) ----------------
__device__ float    g_thresh[BSZ];           // pos_sim - MARGIN, or FLT_MAX if !has_q
__device__ float    g_na[BSZ];
__device__ float    g_sa[BSZ];
__device__ float    g_dap[BSZ];
__device__ int      g_nneg[BSZ * KNEG];
__device__ float    g_nb[MROW];
__device__ float    g_sb[MROW];
__device__ unsigned g_nonneg[MROW * (BSZ / 32)];  // [j][g] bitmask over i
__device__ double   g_total;
__device__ int      g_count;

__inline__ __device__ float warpReduceSum(float v) {
    #pragma unroll
    for (int o = 16; o > 0; o >>= 1) v += __shfl_down_sync(0xffffffffu, v, o);
    return v;
}
__inline__ __device__ int warpReduceSumI(int v) {
    #pragma unroll
    for (int o = 16; o > 0; o >>= 1) v += __shfl_down_sync(0xffffffffu, v, o);
    return v;
}

// ---------------- Kernel A: per-query setup ----------------
// one block per i (256 blocks x 128 threads)
__global__ void setup_kernel(const float* __restrict__ col,
                             const float* __restrict__ row,
                             const int* __restrict__ targets_col,
                             const int* __restrict__ qidxs,
                             const int* __restrict__ nnegs) {
    int i = blockIdx.x;
    int tid = threadIdx.x;
    const float* q = col + (size_t)i * DIM;
    const float* p = row + (size_t)(BSZ + i) * DIM;

    float na = 0.f, sa = 0.f, ps = 0.f, dap2 = 0.f;
    for (int k = tid; k < DIM; k += blockDim.x) {
        float qv = q[k], pv = p[k];
        na += qv * qv;
        sa += qv;
        ps += qv * pv;
        float dlt = qv - pv + EPS_F;
        dap2 += dlt * dlt;
    }
    __shared__ float sh[4][4];
    int w = tid >> 5, l = tid & 31;
    na   = warpReduceSum(na);
    sa   = warpReduceSum(sa);
    ps   = warpReduceSum(ps);
    dap2 = warpReduceSum(dap2);
    if (l == 0) { sh[0][w] = na; sh[1][w] = sa; sh[2][w] = ps; sh[3][w] = dap2; }
    __syncthreads();
    if (tid == 0) {
        na = 0.f; sa = 0.f; ps = 0.f; dap2 = 0.f;
        for (int k = 0; k < 4; k++) { na += sh[0][k]; sa += sh[1][k]; ps += sh[2][k]; dap2 += sh[3][k]; }
        int tc = targets_col[i];
        int qloc = 0, has = 0;
        for (int j = 0; j < BSZ; j++) {
            if (qidxs[j] == tc) { qloc = j; has = 1; break; }
        }
        g_thresh[i] = has ? (ps - MARGIN_F) : FLT_MAX;
        g_na[i] = na;
        g_sa[i] = sa;
        g_dap[i] = sqrtf(dap2);
        for (int k = 0; k < KNEG; k++) g_nneg[i * KNEG + k] = nnegs[qloc * KNEG + k];
        if (i == 0) { g_total = 0.0; g_count = 0; }
    }
}

// ---------------- Kernel C: per-row stats + nonneg bitmask ----------------
// one warp per row j; 8 warps per block
__global__ void rowstats_kernel(const float* __restrict__ row,
                                const int* __restrict__ targets_row) {
    __shared__ int s_nneg[BSZ * KNEG];
    int tid = threadIdx.x;
    for (int x = tid; x < BSZ * KNEG; x += blockDim.x) s_nneg[x] = g_nneg[x];
    __syncthreads();

    int w = tid >> 5, l = tid & 31;
    int j = blockIdx.x * 8 + w;

    const float4* r4 = (const float4*)(row + (size_t)j * DIM);
    float nb = 0.f, sb = 0.f;
    #pragma unroll
    for (int t = 0; t < 4; t++) {
        float4 v = r4[l + 32 * t];
        nb += v.x * v.x + v.y * v.y + v.z * v.z + v.w * v.w;
        sb += v.x + v.y + v.z + v.w;
    }
    nb = warpReduceSum(nb);
    sb = warpReduceSum(sb);

    int t = targets_row[j];
    #pragma unroll
    for (int g = 0; g < 8; g++) {
        int i = g * 32 + l;
        bool m = false;
        #pragma unroll
        for (int k = 0; k < KNEG; k++) m = m || (s_nneg[i * KNEG + k] == t);
        unsigned word = __ballot_sync(0xffffffffu, m);
        if (l == 0) g_nonneg[(size_t)j * 8 + g] = word;
    }
    if (l == 0) { g_nb[j] = nb; g_sb[j] = sb; }
}

// ---------------- Kernel B: fused SGEMM + triplet epilogue ----------------
// 128x128 tile, BK=16, 256 threads, 8x8 micro-tile, double-buffered smem
#define STORE_A(buf, c, r, v) { As[buf][(c)+0][r]=(v).x; As[buf][(c)+1][r]=(v).y; As[buf][(c)+2][r]=(v).z; As[buf][(c)+3][r]=(v).w; }
#define STORE_B(buf, c, r, v) { Bs[buf][(c)+0][r]=(v).x; Bs[buf][(c)+1][r]=(v).y; Bs[buf][(c)+2][r]=(v).z; Bs[buf][(c)+3][r]=(v).w; }

__global__ __launch_bounds__(256)
void main_kernel(const float* __restrict__ Aq, const float* __restrict__ Brow) {
    __shared__ float As[2][16][128];
    __shared__ float Bs[2][16][128];
    __shared__ float s_th[128], s_na[128], s_sa[128], s_dap[128];
    __shared__ float s_nb[128], s_sb[128];
    __shared__ unsigned s_nn[128][4];

    int tid = threadIdx.x;
    int tx = tid & 15, ty = tid >> 4;
    int i0 = blockIdx.y * 128, j0 = blockIdx.x * 128;
    const float* Ap = Aq + (size_t)i0 * DIM;
    const float* Bp = Brow + (size_t)j0 * DIM;

    float acc[8][8];
    #pragma unroll
    for (int a = 0; a < 8; a++)
        #pragma unroll
        for (int b = 0; b < 8; b++) acc[a][b] = 0.f;

    // loader mapping: 512 float4 per 128x16 chunk, 2 per thread
    int lin0 = tid, lin1 = tid + 256;
    int r0 = lin0 >> 2, c0 = (lin0 & 3) << 2;
    int r1 = lin1 >> 2, c1 = (lin1 & 3) << 2;

    // prologue: chunk 0 -> buf 0
    {
        float4 a0 = *(const float4*)(Ap + (size_t)r0 * DIM + c0);
        float4 a1 = *(const float4*)(Ap + (size_t)r1 * DIM + c1);
        float4 b0 = *(const float4*)(Bp + (size_t)r0 * DIM + c0);
        float4 b1 = *(const float4*)(Bp + (size_t)r1 * DIM + c1);
        STORE_A(0, c0, r0, a0);
        STORE_A(0, c1, r1, a1);
        STORE_B(0, c0, r0, b0);
        STORE_B(0, c1, r1, b1);
    }
    __syncthreads();

    const int NKT = DIM / 16;  // 32
    #pragma unroll 1
    for (int kt = 0; kt < NKT; kt++) {
        int buf = kt & 1;
        float4 na0, na1, nb0, nb1;
        if (kt + 1 < NKT) {
            int koff = (kt + 1) * 16;
            na0 = *(const float4*)(Ap + (size_t)r0 * DIM + koff + c0);
            na1 = *(const float4*)(Ap + (size_t)r1 * DIM + koff + c1);
            nb0 = *(const float4*)(Bp + (size_t)r0 * DIM + koff + c0);
            nb1 = *(const float4*)(Bp + (size_t)r1 * DIM + koff + c1);
        }
        #pragma unroll
        for (int kk = 0; kk < 16; kk++) {
            float a[8], b[8];
            *(float4*)(a)     = *(const float4*)&As[buf][kk][ty * 8];
            *(float4*)(a + 4) = *(const float4*)&As[buf][kk][ty * 8 + 4];
            *(float4*)(b)     = *(const float4*)&Bs[buf][kk][tx * 8];
            *(float4*)(b + 4) = *(const float4*)&Bs[buf][kk][tx * 8 + 4];
            #pragma unroll
            for (int ii = 0; ii < 8; ii++)
                #pragma unroll
                for (int jj = 0; jj < 8; jj++)
                    acc[ii][jj] = fmaf(a[ii], b[jj], acc[ii][jj]);
        }
        if (kt + 1 < NKT) {
            int nbuf = buf ^ 1;
            STORE_A(nbuf, c0, r0, na0);
            STORE_A(nbuf, c1, r1, na1);
            STORE_B(nbuf, c0, r0, nb0);
            STORE_B(nbuf, c1, r1, nb1);
        }
        __syncthreads();
    }

    // epilogue param preload
    if (tid < 128) {
        s_th[tid]  = g_thresh[i0 + tid];
        s_na[tid]  = g_na[i0 + tid];
        s_sa[tid]  = g_sa[i0 + tid];
        s_dap[tid] = g_dap[i0 + tid];
        s_nb[tid]  = g_nb[j0 + tid];
        s_sb[tid]  = g_sb[j0 + tid];
        int gw = i0 >> 5;
        #pragma unroll
        for (int c = 0; c < 4; c++)
            s_nn[tid][c] = g_nonneg[(size_t)(j0 + tid) * 8 + gw + c];
    }
    __syncthreads();

    float sumtl = 0.f;
    int cnt = 0;
    #pragma unroll
    for (int jj = 0; jj < 8; jj++) {
        int jl = tx * 8 + jj;
        float nb = s_nb[jl], sb = s_sb[jl];
        #pragma unroll
        for (int ii = 0; ii < 8; ii++) {
            int il = ty * 8 + ii;
            float s = acc[ii][jj];
            if (s > s_th[il]) {
                if (!((s_nn[jl][il >> 5] >> (il & 31)) & 1u)) {
                    cnt++;
                    float dan2 = s_na[il] + nb - 2.0f * s
                               + 2.0f * EPS_F * (s_sa[il] - sb)
                               + (float)DIM * EPS_F * EPS_F;
                    float dan = sqrtf(fmaxf(dan2, 0.0f));
                    float tl = s_dap[il] - dan + TMARGIN_F;
                    if (tl > 0.0f) sumtl += tl;
                }
            }
        }
    }
    sumtl = warpReduceSum(sumtl);
    cnt = warpReduceSumI(cnt);
    if ((tid & 31) == 0 && cnt > 0) {
        atomicAdd(&g_total, (double)sumtl);
        atomicAdd(&g_count, cnt);
    }
}

// ---------------- Kernel D: finalize ----------------
__global__ void finalize_kernel(float* __restrict__ out) {
    int c = g_count;
    out[0] = (c > 0) ? (float)(g_total / (double)c) : 0.0f;
}

extern "C" void kernel_launch(void* const* d_in, const int* in_sizes, int n_in,
                              void* d_out, int out_size) {
    const float* inputs_col  = (const float*)d_in[0];
    const float* inputs_row  = (const float*)d_in[1];
    const int*   targets_col = (const int*)d_in[2];
    const int*   targets_row = (const int*)d_in[3];
    const int*   qidxs       = (const int*)d_in[4];
    // d_in[5] = pidxs: dead code in the reference loss
    const int*   nnegs       = (const int*)d_in[6];

    setup_kernel<<<BSZ, 128>>>(inputs_col, inputs_row, targets_col, qidxs, nnegs);
    rowstats_kernel<<<MROW / 8, 256>>>(inputs_row, targets_row);
    dim3 grid(MROW / 128, BSZ / 128);
    main_kernel<<<grid, 256>>>(inputs_col, inputs_row);
    finalize_kernel<<<1, 1>>>((float*)d_out);
}

// round 3
// speedup vs baseline: 3.0713x; 3.0713x over previous
#include <cuda_runtime.h>
#include <cuda_bf16.h>
#include <math.h>
#include <float.h>
#include <stdint.h>

#define BSZ   256
#define MROW  32768
#define DIM   512
#define KNEG  10
#define MARGIN_F 0.1f
#define EPS_F 1e-6f
#define TMARGIN_F 0.31622776601683794f

#define BN 128            // j rows per CTA
#define BKC 32            // K per chunk (bf16)
#define NCHUNK (DIM / BKC)  // 16
#define PADK 40           // padded k-stride in bf16 elems (80 B, 16B-aligned, ldsm conflict-free)

// dynamic smem layout (bytes)
#define A_T0 0
#define A_T1 20480              // 256*40*2
#define B_T0 40960
#define B_T1 51200              // + 128*40*2
#define SMEM_DYN 61440
// epilogue tables overlay the A0 buffer
#define T_TH  0
#define T_NA  1024
#define T_SA  2048
#define T_DAP 3072
#define T_NB  4096
#define T_SB  4608
#define T_NN  5120              // 128*8 u32 = 4096 B

// ---------------- scratch globals ----------------
__device__ float         g_thresh[BSZ];
__device__ float         g_na[BSZ];
__device__ float         g_sa[BSZ];
__device__ float         g_dap[BSZ];
__device__ int           g_nneg[BSZ * KNEG];
__device__ unsigned      g_nonneg[MROW * 8];
__device__ __nv_bfloat16 g_Abf[BSZ * DIM];
__device__ double        g_total;
__device__ int           g_count;

// ---------------- helpers ----------------
__device__ __forceinline__ uint32_t smem_u32(const void* p) {
    uint32_t a;
    asm("{ .reg .u64 t; cvta.to.shared.u64 t, %1; cvt.u32.u64 %0, t; }" : "=r"(a) : "l"(p));
    return a;
}
__device__ __forceinline__ void ldsm_x4(uint32_t* r, uint32_t addr) {
    asm volatile("ldmatrix.sync.aligned.m8n8.x4.shared.b16 {%0,%1,%2,%3}, [%4];"
                 : "=r"(r[0]), "=r"(r[1]), "=r"(r[2]), "=r"(r[3]) : "r"(addr));
}
__device__ __forceinline__ void mma16816(float* d, const uint32_t* a, uint32_t b0, uint32_t b1) {
    asm volatile(
        "mma.sync.aligned.m16n8k16.row.col.f32.bf16.bf16.f32 "
        "{%0,%1,%2,%3}, {%4,%5,%6,%7}, {%8,%9}, {%0,%1,%2,%3};"
        : "+f"(d[0]), "+f"(d[1]), "+f"(d[2]), "+f"(d[3])
        : "r"(a[0]), "r"(a[1]), "r"(a[2]), "r"(a[3]), "r"(b0), "r"(b1));
}
#define CP_ASYNC16(dst, src) \
    asm volatile("cp.async.cg.shared.global [%0], [%1], 16;" :: "r"(dst), "l"(src))
#define CP_COMMIT()  asm volatile("cp.async.commit_group;" ::: "memory")
#define CP_WAIT0()   asm volatile("cp.async.wait_group 0;" ::: "memory")

__inline__ __device__ float warpReduceSum(float v) {
    #pragma unroll
    for (int o = 16; o > 0; o >>= 1) v += __shfl_down_sync(0xffffffffu, v, o);
    return v;
}
__inline__ __device__ int warpReduceSumI(int v) {
    #pragma unroll
    for (int o = 16; o > 0; o >>= 1) v += __shfl_down_sync(0xffffffffu, v, o);
    return v;
}
__device__ __forceinline__ uint32_t packbf(float x, float y) {
    __nv_bfloat162 t = __float22bfloat162_rn(make_float2(x, y));
    return *(uint32_t*)&t;
}

// ---------------- Kernel A: per-query setup + A bf16 conversion ----------------
__global__ void setup_kernel(const float* __restrict__ col,
                             const float* __restrict__ row,
                             const int* __restrict__ targets_col,
                             const int* __restrict__ qidxs,
                             const int* __restrict__ nnegs) {
    int i = blockIdx.x;
    int tid = threadIdx.x;
    const float* q = col + (size_t)i * DIM;
    const float* p = row + (size_t)(BSZ + i) * DIM;

    float na = 0.f, sa = 0.f, ps = 0.f, dap2 = 0.f;
    for (int k = tid; k < DIM; k += blockDim.x) {
        float qv = q[k], pv = p[k];
        na += qv * qv;
        sa += qv;
        ps += qv * pv;
        float dlt = qv - pv + EPS_F;
        dap2 += dlt * dlt;
        g_Abf[i * DIM + k] = __float2bfloat16_rn(qv);
    }
    __shared__ float sh[4][4];
    int w = tid >> 5, l = tid & 31;
    na = warpReduceSum(na); sa = warpReduceSum(sa);
    ps = warpReduceSum(ps); dap2 = warpReduceSum(dap2);
    if (l == 0) { sh[0][w] = na; sh[1][w] = sa; sh[2][w] = ps; sh[3][w] = dap2; }
    __syncthreads();
    if (tid == 0) {
        na = 0.f; sa = 0.f; ps = 0.f; dap2 = 0.f;
        for (int k = 0; k < 4; k++) { na += sh[0][k]; sa += sh[1][k]; ps += sh[2][k]; dap2 += sh[3][k]; }
        int tc = targets_col[i];
        int qloc = 0, has = 0;
        for (int j = 0; j < BSZ; j++) if (qidxs[j] == tc) { qloc = j; has = 1; break; }
        g_thresh[i] = has ? (ps - MARGIN_F) : FLT_MAX;
        g_na[i] = na; g_sa[i] = sa; g_dap[i] = sqrtf(dap2);
        for (int k = 0; k < KNEG; k++) g_nneg[i * KNEG + k] = nnegs[qloc * KNEG + k];
        if (i == 0) { g_total = 0.0; g_count = 0; }
    }
}

// ---------------- Kernel B: nonneg bitmask ----------------
__global__ void mask_kernel(const int* __restrict__ targets_row) {
    __shared__ int s_nneg[BSZ * KNEG];
    int tid = threadIdx.x;
    for (int x = tid; x < BSZ * KNEG; x += blockDim.x) s_nneg[x] = g_nneg[x];
    __syncthreads();
    int w = tid >> 5, l = tid & 31;
    int j = blockIdx.x * 8 + w;
    int t = targets_row[j];
    #pragma unroll
    for (int g = 0; g < 8; g++) {
        int i = g * 32 + l;
        bool m = false;
        #pragma unroll
        for (int k = 0; k < KNEG; k++) m = m || (s_nneg[i * KNEG + k] == t);
        unsigned word = __ballot_sync(0xffffffffu, m);
        if (l == 0) g_nonneg[(size_t)j * 8 + g] = word;
    }
}

// ---------------- Kernel C: bf16 mma.sync GEMM + fused triplet epilogue ----------------
__global__ __launch_bounds__(512)
void gemm_kernel(const float* __restrict__ Brow) {
    extern __shared__ char dsm[];
    __shared__ float red_s[16];
    __shared__ int   red_c[16];

    uint32_t sb = smem_u32(dsm);
    int tid = threadIdx.x;
    int wid = tid >> 5, lid = tid & 31;
    int j0 = blockIdx.x * BN;

    int q  = tid >> 2;      // 0..127
    int l4 = tid & 3;

    // warp tiling: 4 (i) x 4 (j)
    int wi = wid >> 2, wj = wid & 3;
    int i0w = wi * 64, j0w = wj * 32;

    float acc[4][4][4];
    #pragma unroll
    for (int a = 0; a < 4; a++)
        #pragma unroll
        for (int b = 0; b < 4; b++)
            #pragma unroll
            for (int c = 0; c < 4; c++) acc[a][b][c] = 0.f;

    float nbacc = 0.f, sbacc = 0.f;

    // per-lane ldsm address components (byte offsets within a tile)
    uint32_t a_lane = (uint32_t)((lid & 15) * (PADK * 2) + (lid >> 4) * 16);
    uint32_t b_lane = (uint32_t)(((lid & 7) + ((lid >> 4) & 1) * 8) * (PADK * 2) + ((lid >> 3) & 1) * 16);

    const float* Bg = Brow + (size_t)(j0 + q) * DIM + l4 * 8;

    // ---- prologue: chunk 0 ----
    {
        // A via cp.async (2 granules per thread)
        #pragma unroll
        for (int p = 0; p < 2; p++) {
            int g = tid + p * 512;
            int row = g >> 2, h = g & 3;
            CP_ASYNC16(sb + A_T0 + row * (PADK * 2) + h * 16,
                       (const char*)(g_Abf + row * DIM + h * 8));
        }
        CP_COMMIT();
        float4 b0 = *(const float4*)(Bg + 0);
        float4 b1 = *(const float4*)(Bg + 4);
        nbacc += b0.x*b0.x + b0.y*b0.y + b0.z*b0.z + b0.w*b0.w
               + b1.x*b1.x + b1.y*b1.y + b1.z*b1.z + b1.w*b1.w;
        sbacc += b0.x + b0.y + b0.z + b0.w + b1.x + b1.y + b1.z + b1.w;
        uint4 pk;
        pk.x = packbf(b0.x, b0.y); pk.y = packbf(b0.z, b0.w);
        pk.z = packbf(b1.x, b1.y); pk.w = packbf(b1.z, b1.w);
        *(uint4*)(dsm + B_T0 + q * (PADK * 2) + l4 * 16) = pk;
        CP_WAIT0();
        __syncthreads();
    }

    #pragma unroll 1
    for (int kt = 0; kt < NCHUNK; kt++) {
        int buf = kt & 1;
        uint32_t Ab = sb + (buf ? A_T1 : A_T0);
        uint32_t Bb = sb + (buf ? B_T1 : B_T0);
        uint32_t AbN = sb + (buf ? A_T0 : A_T1);
        char*    BbN = dsm + (buf ? B_T0 : B_T1);

        float4 b0, b1;
        if (kt < NCHUNK - 1) {
            int kc = (kt + 1) * BKC;
            #pragma unroll
            for (int p = 0; p < 2; p++) {
                int g = tid + p * 512;
                int row = g >> 2, h = g & 3;
                CP_ASYNC16(AbN + row * (PADK * 2) + h * 16,
                           (const char*)(g_Abf + row * DIM + kc + h * 8));
            }
            CP_COMMIT();
            b0 = *(const float4*)(Bg + kc);
            b1 = *(const float4*)(Bg + kc + 4);
        }

        // ---- mma on current buffers ----
        #pragma unroll
        for (int ks = 0; ks < BKC; ks += 16) {
            uint32_t afr[4][4], bfr[2][4];
            #pragma unroll
            for (int mt = 0; mt < 4; mt++)
                ldsm_x4(afr[mt], Ab + (uint32_t)((i0w + mt * 16) * (PADK * 2) + ks * 2) + a_lane);
            #pragma unroll
            for (int np = 0; np < 2; np++)
                ldsm_x4(bfr[np], Bb + (uint32_t)((j0w + np * 16) * (PADK * 2) + ks * 2) + b_lane);
            #pragma unroll
            for (int mt = 0; mt < 4; mt++) {
                #pragma unroll
                for (int np = 0; np < 2; np++) {
                    mma16816(acc[mt][np * 2 + 0], afr[mt], bfr[np][0], bfr[np][1]);
                    mma16816(acc[mt][np * 2 + 1], afr[mt], bfr[np][2], bfr[np][3]);
                }
            }
        }

        if (kt < NCHUNK - 1) {
            nbacc += b0.x*b0.x + b0.y*b0.y + b0.z*b0.z + b0.w*b0.w
                   + b1.x*b1.x + b1.y*b1.y + b1.z*b1.z + b1.w*b1.w;
            sbacc += b0.x + b0.y + b0.z + b0.w + b1.x + b1.y + b1.z + b1.w;
            uint4 pk;
            pk.x = packbf(b0.x, b0.y); pk.y = packbf(b0.z, b0.w);
            pk.z = packbf(b1.x, b1.y); pk.w = packbf(b1.z, b1.w);
            *(uint4*)(BbN + q * (PADK * 2) + l4 * 16) = pk;
            CP_WAIT0();
        }
        __syncthreads();
    }

    // ---- epilogue tables (overlay A0 buffer; safe after final sync) ----
    float*    s_th  = (float*)(dsm + T_TH);
    float*    s_na  = (float*)(dsm + T_NA);
    float*    s_sa  = (float*)(dsm + T_SA);
    float*    s_dap = (float*)(dsm + T_DAP);
    float*    s_nb  = (float*)(dsm + T_NB);
    float*    s_sb  = (float*)(dsm + T_SB);
    unsigned* s_nn  = (unsigned*)(dsm + T_NN);

    // reduce nb/sb across the 4 threads sharing a row
    {
        float v = nbacc;
        v += __shfl_down_sync(0xffffffffu, v, 1);
        v += __shfl_down_sync(0xffffffffu, v, 2);
        float u = sbacc;
        u += __shfl_down_sync(0xffffffffu, u, 1);
        u += __shfl_down_sync(0xffffffffu, u, 2);
        if (l4 == 0) { s_nb[q] = v; s_sb[q] = u; }
    }
    if (tid < 256) {
        s_th[tid]  = g_thresh[tid];
        s_na[tid]  = g_na[tid];
        s_sa[tid]  = g_sa[tid];
        s_dap[tid] = g_dap[tid];
    }
    #pragma unroll
    for (int p = 0; p < 2; p++) {
        int wix = tid * 2 + p;          // 0..1023
        int jloc = wix >> 3, g = wix & 7;
        s_nn[wix] = g_nonneg[(size_t)(j0 + jloc) * 8 + g];
    }
    __syncthreads();

    const float cterm = (float)DIM * EPS_F * EPS_F;
    float sumtl = 0.f;
    int cnt = 0;
    #pragma unroll
    for (int mt = 0; mt < 4; mt++) {
        int i1 = i0w + mt * 16 + (lid >> 2);
        int i2 = i1 + 8;
        float th1 = s_th[i1], na1 = s_na[i1], sa1 = s_sa[i1], dp1 = s_dap[i1];
        float th2 = s_th[i2], na2 = s_na[i2], sa2 = s_sa[i2], dp2 = s_dap[i2];
        int g1 = i1 >> 5, g2 = i2 >> 5;
        unsigned bit1 = 1u << (i1 & 31), bit2 = 1u << (i2 & 31);
        #pragma unroll
        for (int nt = 0; nt < 4; nt++) {
            int jl = j0w + nt * 8 + (lid & 3) * 2;
            #pragma unroll
            for (int c = 0; c < 4; c++) {
                int jj = jl + (c & 1);
                float s = acc[mt][nt][c];
                float th  = (c < 2) ? th1 : th2;
                unsigned bit = (c < 2) ? bit1 : bit2;
                int g = (c < 2) ? g1 : g2;
                if (s > th && !(s_nn[jj * 8 + g] & bit)) {
                    float na = (c < 2) ? na1 : na2;
                    float sa = (c < 2) ? sa1 : sa2;
                    float dp = (c < 2) ? dp1 : dp2;
                    cnt++;
                    float dan2 = na + s_nb[jj] - 2.0f * s
                               + 2.0f * EPS_F * (sa - s_sb[jj]) + cterm;
                    float dan = sqrtf(fmaxf(dan2, 0.0f));
                    float tl = dp - dan + TMARGIN_F;
                    if (tl > 0.0f) sumtl += tl;
                }
            }
        }
    }
    sumtl = warpReduceSum(sumtl);
    cnt   = warpReduceSumI(cnt);
    if (lid == 0) { red_s[wid] = sumtl; red_c[wid] = cnt; }
    __syncthreads();
    if (tid == 0) {
        float ts = 0.f; int tc = 0;
        #pragma unroll
        for (int w = 0; w < 16; w++) { ts += red_s[w]; tc += red_c[w]; }
        if (tc > 0) { atomicAdd(&g_total, (double)ts); atomicAdd(&g_count, tc); }
    }
}

// ---------------- Kernel D: finalize ----------------
__global__ void finalize_kernel(float* __restrict__ out) {
    int c = g_count;
    out[0] = (c > 0) ? (float)(g_total / (double)c) : 0.0f;
}

extern "C" void kernel_launch(void* const* d_in, const int* in_sizes, int n_in,
                              void* d_out, int out_size) {
    const float* inputs_col  = (const float*)d_in[0];
    const float* inputs_row  = (const float*)d_in[1];
    const int*   targets_col = (const int*)d_in[2];
    const int*   targets_row = (const int*)d_in[3];
    const int*   qidxs       = (const int*)d_in[4];
    // d_in[5] = pidxs: dead in the reference loss
    const int*   nnegs       = (const int*)d_in[6];

    cudaFuncSetAttribute(gemm_kernel, cudaFuncAttributeMaxDynamicSharedMemorySize, SMEM_DYN);

    setup_kernel<<<BSZ, 128>>>(inputs_col, inputs_row, targets_col, qidxs, nnegs);
    mask_kernel<<<MROW / 8, 256>>>(targets_row);
    gemm_kernel<<<MROW / BN, 512, SMEM_DYN>>>(inputs_row);
    finalize_kernel<<<1, 1>>>((float*)d_out);
}